// round 1
// baseline (speedup 1.0000x reference)
#include <cuda_runtime.h>

#define N_NODES 100000
#define N_EDGES 3200000
#define N_FEAT  128
#define N_HID   128
#define N_CLASS 16
#define SCAN_NBLK 98   // ceil(100000/1024)

// ---------------- scratch (device globals; no runtime allocation) ----------
__device__ float g_xw1[N_NODES * N_HID];     // x @ W1
__device__ float g_h[N_NODES * N_HID];       // relu(spmm + b1)
__device__ float g_hw4[N_NODES * N_CLASS];   // h @ W4
__device__ int   g_scol[N_EDGES];            // CSR-sorted cols
__device__ float g_sval[N_EDGES];            // CSR-sorted vals
__device__ int   g_cnt[N_NODES];             // degree
__device__ int   g_rowstart[N_NODES];        // exclusive prefix of degree
__device__ int   g_wptr[N_NODES];            // scatter write cursor
__device__ int   g_blocksums[SCAN_NBLK];
__device__ int   g_blockoff[SCAN_NBLK];

// ---------------- CSR build ----------------
__global__ void k_zero_cnt() {
    int i = blockIdx.x * blockDim.x + threadIdx.x;
    if (i < N_NODES) g_cnt[i] = 0;
}

__global__ void k_hist(const int* __restrict__ erow) {
    int e = blockIdx.x * blockDim.x + threadIdx.x;
    if (e < N_EDGES) atomicAdd(&g_cnt[erow[e]], 1);
}

__global__ void k_scan1() {
    __shared__ int s[1024];
    int t = threadIdx.x, b = blockIdx.x;
    int i = b * 1024 + t;
    int v = (i < N_NODES) ? g_cnt[i] : 0;
    s[t] = v;
    __syncthreads();
    #pragma unroll
    for (int off = 1; off < 1024; off <<= 1) {
        int add = (t >= off) ? s[t - off] : 0;
        __syncthreads();
        s[t] += add;
        __syncthreads();
    }
    if (i < N_NODES) g_rowstart[i] = s[t] - v;   // local exclusive
    if (t == 1023) g_blocksums[b] = s[1023];
}

__global__ void k_scan2() {
    if (threadIdx.x == 0) {
        int run = 0;
        for (int b = 0; b < SCAN_NBLK; b++) {
            g_blockoff[b] = run;
            run += g_blocksums[b];
        }
    }
}

__global__ void k_scan3() {
    int t = threadIdx.x, b = blockIdx.x;
    int i = b * 1024 + t;
    if (i < N_NODES) {
        int v = g_rowstart[i] + g_blockoff[b];
        g_rowstart[i] = v;
        g_wptr[i] = v;
    }
}

__global__ void k_scatter(const int* __restrict__ erow,
                          const int* __restrict__ ecol,
                          const float* __restrict__ eval) {
    int e = blockIdx.x * blockDim.x + threadIdx.x;
    if (e >= N_EDGES) return;
    int r = erow[e];
    int p = atomicAdd(&g_wptr[r], 1);
    g_scol[p] = ecol[e];
    g_sval[p] = eval[e];
}

// ---------------- GEMM1: g_xw1 = x @ W1   (100000x128 @ 128x128) ----------
__global__ void k_gemm1(const float* __restrict__ x, const float* __restrict__ W1) {
    __shared__ float As[64][16];
    __shared__ float Bs[16][128];
    int m0 = blockIdx.x * 64;
    int t  = threadIdx.x;       // 0..255
    int tx = t & 31;            // col group (x4)
    int ty = t >> 5;            // row group (x8)

    float acc[8][4];
    #pragma unroll
    for (int i = 0; i < 8; i++)
        #pragma unroll
        for (int j = 0; j < 4; j++) acc[i][j] = 0.f;

    for (int k0 = 0; k0 < 128; k0 += 16) {
        #pragma unroll
        for (int p = 0; p < 4; p++) {
            int idx = t + p * 256;
            int r = idx >> 4, kk = idx & 15;
            int gm = m0 + r;
            As[r][kk] = (gm < N_NODES) ? x[gm * 128 + k0 + kk] : 0.f;
        }
        #pragma unroll
        for (int p = 0; p < 8; p++) {
            int idx = t + p * 256;
            int kk = idx >> 7, n = idx & 127;
            Bs[kk][n] = W1[(k0 + kk) * 128 + n];
        }
        __syncthreads();
        #pragma unroll
        for (int kk = 0; kk < 16; kk++) {
            float ra[8];
            #pragma unroll
            for (int i = 0; i < 8; i++) ra[i] = As[ty * 8 + i][kk];
            float4 rb = ((const float4*)Bs[kk])[tx];
            #pragma unroll
            for (int i = 0; i < 8; i++) {
                acc[i][0] += ra[i] * rb.x;
                acc[i][1] += ra[i] * rb.y;
                acc[i][2] += ra[i] * rb.z;
                acc[i][3] += ra[i] * rb.w;
            }
        }
        __syncthreads();
    }
    #pragma unroll
    for (int i = 0; i < 8; i++) {
        int gm = m0 + ty * 8 + i;
        if (gm < N_NODES) {
            float4 v = make_float4(acc[i][0], acc[i][1], acc[i][2], acc[i][3]);
            *(float4*)&g_xw1[gm * 128 + tx * 4] = v;
        }
    }
}

// ---------------- SPMM1: g_h = relu(A @ g_xw1 + b1), one warp per row -----
__global__ void k_spmm1(const float* __restrict__ b1) {
    int w    = (blockIdx.x * blockDim.x + threadIdx.x) >> 5;
    int lane = threadIdx.x & 31;
    if (w >= N_NODES) return;
    int start = g_rowstart[w];
    int deg   = g_cnt[w];
    int j = start, end = start + deg;
    float4 acc = make_float4(0.f, 0.f, 0.f, 0.f);

    for (; j + 2 <= end; j += 2) {
        int   c0 = g_scol[j];
        int   c1 = g_scol[j + 1];
        float v0 = g_sval[j];
        float v1 = g_sval[j + 1];
        float4 a = *(const float4*)&g_xw1[c0 * 128 + lane * 4];
        float4 b = *(const float4*)&g_xw1[c1 * 128 + lane * 4];
        acc.x += v0 * a.x; acc.y += v0 * a.y; acc.z += v0 * a.z; acc.w += v0 * a.w;
        acc.x += v1 * b.x; acc.y += v1 * b.y; acc.z += v1 * b.z; acc.w += v1 * b.w;
    }
    if (j < end) {
        int   c0 = g_scol[j];
        float v0 = g_sval[j];
        float4 a = *(const float4*)&g_xw1[c0 * 128 + lane * 4];
        acc.x += v0 * a.x; acc.y += v0 * a.y; acc.z += v0 * a.z; acc.w += v0 * a.w;
    }
    float4 bb = *(const float4*)&b1[lane * 4];
    float4 h;
    h.x = fmaxf(acc.x + bb.x, 0.f);
    h.y = fmaxf(acc.y + bb.y, 0.f);
    h.z = fmaxf(acc.z + bb.z, 0.f);
    h.w = fmaxf(acc.w + bb.w, 0.f);
    *(float4*)&g_h[w * 128 + lane * 4] = h;
}

// ---------------- GEMM2: g_hw4 = g_h @ W4  (100000x128 @ 128x16) ----------
// Warp handles 2 rows; 16 lanes per row, one class per lane.
__global__ void k_gemm2(const float* __restrict__ W4) {
    __shared__ float sW4[128 * 16];
    int t = threadIdx.x;
    #pragma unroll
    for (int p = 0; p < 8; p++) sW4[t + p * 256] = W4[t + p * 256];
    __syncthreads();

    int w    = (blockIdx.x * 256 + t) >> 5;
    int lane = t & 31;
    int r    = w * 2 + (lane >> 4);
    int c    = lane & 15;
    if (r >= N_NODES) return;

    const float* hrow = &g_h[r * 128];
    float acc = 0.f;
    #pragma unroll
    for (int k4 = 0; k4 < 32; k4++) {
        float4 hv = *(const float4*)&hrow[k4 * 4];
        acc += hv.x * sW4[(k4 * 4 + 0) * 16 + c];
        acc += hv.y * sW4[(k4 * 4 + 1) * 16 + c];
        acc += hv.z * sW4[(k4 * 4 + 2) * 16 + c];
        acc += hv.w * sW4[(k4 * 4 + 3) * 16 + c];
    }
    g_hw4[r * 16 + c] = acc;
}

// ---------------- SPMM2 + b4 + log_softmax, fused -------------------------
// Warp handles 2 rows; 16 lanes per row, one class per lane.
__global__ void k_spmm2(const float* __restrict__ b4, float* __restrict__ out) {
    int t    = threadIdx.x;
    int w    = (blockIdx.x * 256 + t) >> 5;
    int lane = t & 31;
    int r    = w * 2 + (lane >> 4);
    int c    = lane & 15;
    if (r >= N_NODES) return;

    int start = g_rowstart[r];
    int deg   = g_cnt[r];
    float acc = 0.f;
    for (int j = start; j < start + deg; j++) {
        int   cc = g_scol[j];
        float v  = g_sval[j];
        acc += v * g_hw4[cc * 16 + c];
    }
    float z = acc + b4[c];

    // log-softmax over the 16 classes held by this 16-lane group
    float m = z;
    #pragma unroll
    for (int o = 1; o < 16; o <<= 1)
        m = fmaxf(m, __shfl_xor_sync(0xffffffffu, m, o, 16));
    float e = expf(z - m);
    float s = e;
    #pragma unroll
    for (int o = 1; o < 16; o <<= 1)
        s += __shfl_xor_sync(0xffffffffu, s, o, 16);
    out[r * 16 + c] = z - m - logf(s);
}

// ---------------- launch ---------------------------------------------------
extern "C" void kernel_launch(void* const* d_in, const int* in_sizes, int n_in,
                              void* d_out, int out_size) {
    const float* x    = (const float*)d_in[0];
    const float* eval = (const float*)d_in[1];
    const float* W1   = (const float*)d_in[2];
    const float* b1   = (const float*)d_in[3];
    const float* W4   = (const float*)d_in[4];
    const float* b4   = (const float*)d_in[5];
    const int*   erow = (const int*)d_in[6];
    const int*   ecol = (const int*)d_in[7];
    float*       out  = (float*)d_out;

    // GEMM1 is independent of the CSR build; launch first.
    k_gemm1<<<(N_NODES + 63) / 64, 256>>>(x, W1);

    // CSR build
    k_zero_cnt<<<(N_NODES + 255) / 256, 256>>>();
    k_hist<<<(N_EDGES + 255) / 256, 256>>>(erow);
    k_scan1<<<SCAN_NBLK, 1024>>>();
    k_scan2<<<1, 32>>>();
    k_scan3<<<SCAN_NBLK, 1024>>>();
    k_scatter<<<(N_EDGES + 255) / 256, 256>>>(erow, ecol, eval);

    // layer 1 aggregate + relu
    k_spmm1<<<(N_NODES * 32 + 255) / 256, 256>>>(b1);

    // layer 2
    k_gemm2<<<((N_NODES + 1) / 2 * 32 + 255) / 256, 256>>>(W4);
    k_spmm2<<<((N_NODES + 1) / 2 * 32 + 255) / 256, 256>>>(b4, out);
}

// round 2
// speedup vs baseline: 1.1661x; 1.1661x over previous
#include <cuda_runtime.h>
#include <cuda_fp16.h>

#define N_NODES 100000
#define N_EDGES 3200000
#define N_FEAT  128
#define N_HID   128
#define N_CLASS 16
#define SCAN_NBLK 98   // ceil(100000/1024)

// ---------------- scratch (device globals; no runtime allocation) ----------
__device__ unsigned int g_xw1h[N_NODES * 64];   // x@W1 as half2 pairs (128 halves/row)
__device__ unsigned int g_hh[N_NODES * 64];     // relu(spmm+b1) as half
__device__ __half g_hw4h[N_NODES * N_CLASS];    // h@W4 as half
__device__ int2  g_edge[N_EDGES];               // CSR-sorted {col, val bits}
__device__ int   g_cnt[N_NODES];
__device__ int   g_rowstart[N_NODES];
__device__ int   g_wptr[N_NODES];
__device__ int   g_blocksums[SCAN_NBLK];
__device__ int   g_blockoff[SCAN_NBLK];

// ---------------- f32x2 helpers --------------------------------------------
__device__ __forceinline__ unsigned long long pack2(float lo, float hi) {
    unsigned long long u;
    asm("mov.b64 %0, {%1,%2};" : "=l"(u) : "f"(lo), "f"(hi));
    return u;
}
__device__ __forceinline__ void fma2(unsigned long long& d, unsigned long long a,
                                     unsigned long long b) {
    asm("fma.rn.f32x2 %0, %1, %2, %0;" : "+l"(d) : "l"(a), "l"(b));
}
__device__ __forceinline__ float2 unpack2(unsigned long long u) {
    float lo, hi;
    asm("mov.b64 {%0,%1}, %2;" : "=f"(lo), "=f"(hi) : "l"(u));
    return make_float2(lo, hi);
}

// ---------------- CSR build ----------------
__global__ void k_zero_cnt() {
    int i = blockIdx.x * blockDim.x + threadIdx.x;
    if (i < N_NODES) g_cnt[i] = 0;
}

__global__ void k_hist(const int* __restrict__ erow) {
    int e = blockIdx.x * blockDim.x + threadIdx.x;
    if (e < N_EDGES) atomicAdd(&g_cnt[erow[e]], 1);
}

__global__ void k_scan1() {
    __shared__ int s[1024];
    int t = threadIdx.x, b = blockIdx.x;
    int i = b * 1024 + t;
    int v = (i < N_NODES) ? g_cnt[i] : 0;
    s[t] = v;
    __syncthreads();
    #pragma unroll
    for (int off = 1; off < 1024; off <<= 1) {
        int add = (t >= off) ? s[t - off] : 0;
        __syncthreads();
        s[t] += add;
        __syncthreads();
    }
    if (i < N_NODES) g_rowstart[i] = s[t] - v;   // local exclusive
    if (t == 1023) g_blocksums[b] = s[1023];
}

// parallel scan of the 98 block sums (one block, 128 threads)
__global__ void k_scan2() {
    __shared__ int s[128];
    int t = threadIdx.x;
    int v = (t < SCAN_NBLK) ? g_blocksums[t] : 0;
    s[t] = v;
    __syncthreads();
    #pragma unroll
    for (int off = 1; off < 128; off <<= 1) {
        int add = (t >= off) ? s[t - off] : 0;
        __syncthreads();
        s[t] += add;
        __syncthreads();
    }
    if (t < SCAN_NBLK) g_blockoff[t] = s[t] - v;   // exclusive
}

__global__ void k_scan3() {
    int t = threadIdx.x, b = blockIdx.x;
    int i = b * 1024 + t;
    if (i < N_NODES) {
        int v = g_rowstart[i] + g_blockoff[b];
        g_rowstart[i] = v;
        g_wptr[i] = v;
    }
}

__global__ void k_scatter(const int* __restrict__ erow,
                          const int* __restrict__ ecol,
                          const float* __restrict__ eval) {
    int e = blockIdx.x * blockDim.x + threadIdx.x;
    if (e >= N_EDGES) return;
    int r = erow[e];
    int p = atomicAdd(&g_wptr[r], 1);
    g_edge[p] = make_int2(ecol[e], __float_as_int(eval[e]));
}

// ---------------- GEMM1: g_xw1h = half(x @ W1) -----------------------------
// 64-row tiles, 256 threads, warp owns 8 rows, lane owns 4 cols; f32x2 FMA.
__global__ void k_gemm1(const float* __restrict__ x, const float* __restrict__ W1) {
    __shared__ float As[64][16];
    __shared__ float Bs[16][128];
    int m0 = blockIdx.x * 64;
    int t  = threadIdx.x;       // 0..255
    int tx = t & 31;            // lane: cols tx*4..tx*4+3
    int ty = t >> 5;            // warp: rows ty*8..ty*8+7

    unsigned long long acc[8][2];
    #pragma unroll
    for (int i = 0; i < 8; i++) { acc[i][0] = 0ULL; acc[i][1] = 0ULL; }

    for (int k0 = 0; k0 < 128; k0 += 16) {
        #pragma unroll
        for (int p = 0; p < 4; p++) {
            int idx = t + p * 256;
            int r = idx >> 4, kk = idx & 15;
            int gm = m0 + r;
            As[r][kk] = (gm < N_NODES) ? x[gm * 128 + k0 + kk] : 0.f;
        }
        #pragma unroll
        for (int p = 0; p < 8; p++) {
            int idx = t + p * 256;
            int kk = idx >> 7, n = idx & 127;
            Bs[kk][n] = W1[(k0 + kk) * 128 + n];
        }
        __syncthreads();
        #pragma unroll
        for (int kk = 0; kk < 16; kk++) {
            float4 rb = ((const float4*)Bs[kk])[tx];
            unsigned long long b0 = pack2(rb.x, rb.y);
            unsigned long long b1 = pack2(rb.z, rb.w);
            #pragma unroll
            for (int i = 0; i < 8; i++) {
                float a = As[ty * 8 + i][kk];
                unsigned long long ra = pack2(a, a);
                fma2(acc[i][0], ra, b0);
                fma2(acc[i][1], ra, b1);
            }
        }
        __syncthreads();
    }
    #pragma unroll
    for (int i = 0; i < 8; i++) {
        int gm = m0 + ty * 8 + i;
        if (gm < N_NODES) {
            float2 p0 = unpack2(acc[i][0]);
            float2 p1 = unpack2(acc[i][1]);
            __half2 h0 = __floats2half2_rn(p0.x, p0.y);
            __half2 h1 = __floats2half2_rn(p1.x, p1.y);
            uint2 v = make_uint2(*(unsigned*)&h0, *(unsigned*)&h1);
            *(uint2*)&g_xw1h[gm * 64 + tx * 2] = v;
        }
    }
}

// ---------------- SPMM1: g_hh = half(relu(A @ xw1 + b1)), warp per row -----
__device__ __forceinline__ void fma_row(float4& acc, float v, uint2 q) {
    __half2 h0 = *(__half2*)&q.x;
    __half2 h1 = *(__half2*)&q.y;
    float2 f0 = __half22float2(h0);
    float2 f1 = __half22float2(h1);
    acc.x = fmaf(v, f0.x, acc.x);
    acc.y = fmaf(v, f0.y, acc.y);
    acc.z = fmaf(v, f1.x, acc.z);
    acc.w = fmaf(v, f1.y, acc.w);
}

__global__ void k_spmm1(const float* __restrict__ b1) {
    int w    = (blockIdx.x * blockDim.x + threadIdx.x) >> 5;
    int lane = threadIdx.x & 31;
    if (w >= N_NODES) return;
    int start = g_rowstart[w];
    int deg   = g_cnt[w];
    const int2* ep = g_edge + start;
    float4 acc = make_float4(0.f, 0.f, 0.f, 0.f);

    int j = 0;
    for (; j + 4 <= deg; j += 4) {
        int2 e0 = ep[j], e1 = ep[j + 1], e2 = ep[j + 2], e3 = ep[j + 3];
        uint2 q0 = *(const uint2*)&g_xw1h[e0.x * 64 + lane * 2];
        uint2 q1 = *(const uint2*)&g_xw1h[e1.x * 64 + lane * 2];
        uint2 q2 = *(const uint2*)&g_xw1h[e2.x * 64 + lane * 2];
        uint2 q3 = *(const uint2*)&g_xw1h[e3.x * 64 + lane * 2];
        fma_row(acc, __int_as_float(e0.y), q0);
        fma_row(acc, __int_as_float(e1.y), q1);
        fma_row(acc, __int_as_float(e2.y), q2);
        fma_row(acc, __int_as_float(e3.y), q3);
    }
    for (; j < deg; j++) {
        int2 e0 = ep[j];
        uint2 q0 = *(const uint2*)&g_xw1h[e0.x * 64 + lane * 2];
        fma_row(acc, __int_as_float(e0.y), q0);
    }

    float4 bb = *(const float4*)&b1[lane * 4];
    float hx = fmaxf(acc.x + bb.x, 0.f);
    float hy = fmaxf(acc.y + bb.y, 0.f);
    float hz = fmaxf(acc.z + bb.z, 0.f);
    float hw = fmaxf(acc.w + bb.w, 0.f);
    __half2 h0 = __floats2half2_rn(hx, hy);
    __half2 h1 = __floats2half2_rn(hz, hw);
    uint2 v = make_uint2(*(unsigned*)&h0, *(unsigned*)&h1);
    *(uint2*)&g_hh[w * 64 + lane * 2] = v;
}

// ---------------- GEMM2: g_hw4h = half(g_hh @ W4) --------------------------
// Warp handles 2 rows; 16 lanes per row, one class per lane.
__global__ void k_gemm2(const float* __restrict__ W4) {
    __shared__ float sW4[128 * 16];
    int t = threadIdx.x;
    #pragma unroll
    for (int p = 0; p < 8; p++) sW4[t + p * 256] = W4[t + p * 256];
    __syncthreads();

    int w    = (blockIdx.x * 256 + t) >> 5;
    int lane = t & 31;
    int r    = w * 2 + (lane >> 4);
    int c    = lane & 15;
    if (r >= N_NODES) return;

    const uint2* hrow = (const uint2*)&g_hh[r * 64];
    float acc = 0.f;
    #pragma unroll
    for (int kk = 0; kk < 32; kk++) {
        uint2 q = hrow[kk];
        __half2 h0 = *(__half2*)&q.x;
        __half2 h1 = *(__half2*)&q.y;
        float2 f0 = __half22float2(h0);
        float2 f1 = __half22float2(h1);
        acc = fmaf(f0.x, sW4[(kk * 4 + 0) * 16 + c], acc);
        acc = fmaf(f0.y, sW4[(kk * 4 + 1) * 16 + c], acc);
        acc = fmaf(f1.x, sW4[(kk * 4 + 2) * 16 + c], acc);
        acc = fmaf(f1.y, sW4[(kk * 4 + 3) * 16 + c], acc);
    }
    g_hw4h[r * 16 + c] = __float2half_rn(acc);
}

// ---------------- SPMM2 + b4 + log_softmax, fused --------------------------
__global__ void k_spmm2(const float* __restrict__ b4, float* __restrict__ out) {
    int t    = threadIdx.x;
    int w    = (blockIdx.x * 256 + t) >> 5;
    int lane = t & 31;
    int r    = w * 2 + (lane >> 4);
    int c    = lane & 15;
    if (r >= N_NODES) return;

    int start = g_rowstart[r];
    int deg   = g_cnt[r];
    const int2* ep = g_edge + start;
    float acc = 0.f;
    int j = 0;
    for (; j + 2 <= deg; j += 2) {
        int2 e0 = ep[j], e1 = ep[j + 1];
        float h0 = __half2float(g_hw4h[e0.x * 16 + c]);
        float h1 = __half2float(g_hw4h[e1.x * 16 + c]);
        acc = fmaf(__int_as_float(e0.y), h0, acc);
        acc = fmaf(__int_as_float(e1.y), h1, acc);
    }
    if (j < deg) {
        int2 e0 = ep[j];
        acc = fmaf(__int_as_float(e0.y), __half2float(g_hw4h[e0.x * 16 + c]), acc);
    }
    float z = acc + b4[c];

    // log-softmax over the 16 classes held by this 16-lane group
    float m = z;
    #pragma unroll
    for (int o = 1; o < 16; o <<= 1)
        m = fmaxf(m, __shfl_xor_sync(0xffffffffu, m, o, 16));
    float e = expf(z - m);
    float s = e;
    #pragma unroll
    for (int o = 1; o < 16; o <<= 1)
        s += __shfl_xor_sync(0xffffffffu, s, o, 16);
    out[r * 16 + c] = z - m - logf(s);
}

// ---------------- launch ---------------------------------------------------
extern "C" void kernel_launch(void* const* d_in, const int* in_sizes, int n_in,
                              void* d_out, int out_size) {
    const float* x    = (const float*)d_in[0];
    const float* eval = (const float*)d_in[1];
    const float* W1   = (const float*)d_in[2];
    const float* b1   = (const float*)d_in[3];
    const float* W4   = (const float*)d_in[4];
    const float* b4   = (const float*)d_in[5];
    const int*   erow = (const int*)d_in[6];
    const int*   ecol = (const int*)d_in[7];
    float*       out  = (float*)d_out;

    // GEMM1 independent of the CSR build; launch first.
    k_gemm1<<<(N_NODES + 63) / 64, 256>>>(x, W1);

    // CSR build
    k_zero_cnt<<<(N_NODES + 255) / 256, 256>>>();
    k_hist<<<(N_EDGES + 255) / 256, 256>>>(erow);
    k_scan1<<<SCAN_NBLK, 1024>>>();
    k_scan2<<<1, 128>>>();
    k_scan3<<<SCAN_NBLK, 1024>>>();
    k_scatter<<<(N_EDGES + 255) / 256, 256>>>(erow, ecol, eval);

    // layer 1 aggregate + relu
    k_spmm1<<<(N_NODES * 32 + 255) / 256, 256>>>(b1);

    // layer 2
    k_gemm2<<<((N_NODES + 1) / 2 * 32 + 255) / 256, 256>>>(W4);
    k_spmm2<<<((N_NODES + 1) / 2 * 32 + 255) / 256, 256>>>(b4, out);
}

// round 3
// speedup vs baseline: 1.2135x; 1.0406x over previous
#include <cuda_runtime.h>
#include <cuda_fp16.h>

#define N_NODES 100000
#define N_EDGES 3200000
#define N_FEAT  128
#define N_HID   128
#define N_CLASS 16
#define SCAN_NBLK 98   // ceil(100000/1024)

// ---------------- scratch (device globals; no runtime allocation) ----------
__device__ unsigned int g_xw1h[N_NODES * 64];   // x@W1 as half2 pairs (128 halves/row)
__device__ unsigned int g_hh[N_NODES * 64];     // relu(spmm+b1) as half
__device__ __half g_hw4h[N_NODES * N_CLASS];    // h@W4 as half
__device__ int2  g_edge[N_EDGES];               // CSR-sorted {col, val bits}
__device__ int   g_cnt[N_NODES];
__device__ int   g_rowstart[N_NODES];
__device__ int   g_wptr[N_NODES];
__device__ int   g_blocksums[SCAN_NBLK];

// ---------------- f32x2 helpers --------------------------------------------
__device__ __forceinline__ unsigned long long pack2(float lo, float hi) {
    unsigned long long u;
    asm("mov.b64 %0, {%1,%2};" : "=l"(u) : "f"(lo), "f"(hi));
    return u;
}
__device__ __forceinline__ void fma2(unsigned long long& d, unsigned long long a,
                                     unsigned long long b) {
    asm("fma.rn.f32x2 %0, %1, %2, %0;" : "+l"(d) : "l"(a), "l"(b));
}
__device__ __forceinline__ float2 unpack2(unsigned long long u) {
    float lo, hi;
    asm("mov.b64 {%0,%1}, %2;" : "=f"(lo), "=f"(hi) : "l"(u));
    return make_float2(lo, hi);
}

// ---------------- CSR build ----------------
__global__ void k_zero_cnt() {
    int i = blockIdx.x * blockDim.x + threadIdx.x;
    if (i < N_NODES) g_cnt[i] = 0;
}

__global__ void k_hist(const int* __restrict__ erow) {
    int e = blockIdx.x * blockDim.x + threadIdx.x;
    if (e < N_EDGES) atomicAdd(&g_cnt[erow[e]], 1);
}

__global__ void k_scan1() {
    __shared__ int s[1024];
    int t = threadIdx.x, b = blockIdx.x;
    int i = b * 1024 + t;
    int v = (i < N_NODES) ? g_cnt[i] : 0;
    s[t] = v;
    __syncthreads();
    #pragma unroll
    for (int off = 1; off < 1024; off <<= 1) {
        int add = (t >= off) ? s[t - off] : 0;
        __syncthreads();
        s[t] += add;
        __syncthreads();
    }
    if (i < N_NODES) g_rowstart[i] = s[t] - v;   // local exclusive
    if (t == 1023) g_blocksums[b] = s[1023];
}

// merged scan2+scan3: every block locally scans the 98 block sums (cheap,
// L2-hit loads), then applies its own offset. Saves a launch + dep edge.
__global__ void k_scan23() {
    __shared__ int s[128];
    int t = threadIdx.x, b = blockIdx.x;
    if (t < 128) s[t] = (t < SCAN_NBLK) ? g_blocksums[t] : 0;
    __syncthreads();
    #pragma unroll
    for (int off = 1; off < 128; off <<= 1) {
        int add = (t >= off && t < 128) ? s[t - off] : 0;
        __syncthreads();
        if (t < 128) s[t] += add;
        __syncthreads();
    }
    int boff = (b == 0) ? 0 : s[b - 1];   // exclusive offset for this block
    int i = b * 1024 + t;
    if (i < N_NODES) {
        int v = g_rowstart[i] + boff;
        g_rowstart[i] = v;
        g_wptr[i] = v;
    }
}

__global__ void k_scatter(const int* __restrict__ erow,
                          const int* __restrict__ ecol,
                          const float* __restrict__ eval) {
    int e = blockIdx.x * blockDim.x + threadIdx.x;
    if (e >= N_EDGES) return;
    int r = erow[e];
    int p = atomicAdd(&g_wptr[r], 1);
    g_edge[p] = make_int2(ecol[e], __float_as_int(eval[e]));
}

// ---------------- GEMM1: g_xw1h = half(x @ W1) -----------------------------
// 64-row tiles, 256 threads, warp owns 8 rows, lane owns 4 cols; f32x2 FMA.
__global__ void k_gemm1(const float* __restrict__ x, const float* __restrict__ W1) {
    __shared__ float As[64][16];
    __shared__ float Bs[16][128];
    int m0 = blockIdx.x * 64;
    int t  = threadIdx.x;       // 0..255
    int tx = t & 31;            // lane: cols tx*4..tx*4+3
    int ty = t >> 5;            // warp: rows ty*8..ty*8+7

    unsigned long long acc[8][2];
    #pragma unroll
    for (int i = 0; i < 8; i++) { acc[i][0] = 0ULL; acc[i][1] = 0ULL; }

    for (int k0 = 0; k0 < 128; k0 += 16) {
        #pragma unroll
        for (int p = 0; p < 4; p++) {
            int idx = t + p * 256;
            int r = idx >> 4, kk = idx & 15;
            int gm = m0 + r;
            As[r][kk] = (gm < N_NODES) ? x[gm * 128 + k0 + kk] : 0.f;
        }
        #pragma unroll
        for (int p = 0; p < 8; p++) {
            int idx = t + p * 256;
            int kk = idx >> 7, n = idx & 127;
            Bs[kk][n] = W1[(k0 + kk) * 128 + n];
        }
        __syncthreads();
        #pragma unroll
        for (int kk = 0; kk < 16; kk++) {
            float4 rb = ((const float4*)Bs[kk])[tx];
            unsigned long long b0 = pack2(rb.x, rb.y);
            unsigned long long b1 = pack2(rb.z, rb.w);
            #pragma unroll
            for (int i = 0; i < 8; i++) {
                float a = As[ty * 8 + i][kk];
                unsigned long long ra = pack2(a, a);
                fma2(acc[i][0], ra, b0);
                fma2(acc[i][1], ra, b1);
            }
        }
        __syncthreads();
    }
    #pragma unroll
    for (int i = 0; i < 8; i++) {
        int gm = m0 + ty * 8 + i;
        if (gm < N_NODES) {
            float2 p0 = unpack2(acc[i][0]);
            float2 p1 = unpack2(acc[i][1]);
            __half2 h0 = __floats2half2_rn(p0.x, p0.y);
            __half2 h1 = __floats2half2_rn(p1.x, p1.y);
            uint2 v = make_uint2(*(unsigned*)&h0, *(unsigned*)&h1);
            *(uint2*)&g_xw1h[gm * 64 + tx * 2] = v;
        }
    }
}

// ---------------- SPMM1: g_hh = half(relu(A @ xw1 + b1)), warp per row -----
__device__ __forceinline__ void fma_row(float4& acc, float v, uint2 q) {
    __half2 h0 = *(__half2*)&q.x;
    __half2 h1 = *(__half2*)&q.y;
    float2 f0 = __half22float2(h0);
    float2 f1 = __half22float2(h1);
    acc.x = fmaf(v, f0.x, acc.x);
    acc.y = fmaf(v, f0.y, acc.y);
    acc.z = fmaf(v, f1.x, acc.z);
    acc.w = fmaf(v, f1.y, acc.w);
}

__global__ void k_spmm1(const float* __restrict__ b1) {
    int w    = (blockIdx.x * blockDim.x + threadIdx.x) >> 5;
    int lane = threadIdx.x & 31;
    if (w >= N_NODES) return;
    int start = g_rowstart[w];
    int deg   = g_cnt[w];
    const int2* ep = g_edge + start;
    float4 acc = make_float4(0.f, 0.f, 0.f, 0.f);

    int j = 0;
    for (; j + 4 <= deg; j += 4) {
        int2 e0 = ep[j], e1 = ep[j + 1], e2 = ep[j + 2], e3 = ep[j + 3];
        uint2 q0 = *(const uint2*)&g_xw1h[e0.x * 64 + lane * 2];
        uint2 q1 = *(const uint2*)&g_xw1h[e1.x * 64 + lane * 2];
        uint2 q2 = *(const uint2*)&g_xw1h[e2.x * 64 + lane * 2];
        uint2 q3 = *(const uint2*)&g_xw1h[e3.x * 64 + lane * 2];
        fma_row(acc, __int_as_float(e0.y), q0);
        fma_row(acc, __int_as_float(e1.y), q1);
        fma_row(acc, __int_as_float(e2.y), q2);
        fma_row(acc, __int_as_float(e3.y), q3);
    }
    for (; j < deg; j++) {
        int2 e0 = ep[j];
        uint2 q0 = *(const uint2*)&g_xw1h[e0.x * 64 + lane * 2];
        fma_row(acc, __int_as_float(e0.y), q0);
    }

    float4 bb = *(const float4*)&b1[lane * 4];
    float hx = fmaxf(acc.x + bb.x, 0.f);
    float hy = fmaxf(acc.y + bb.y, 0.f);
    float hz = fmaxf(acc.z + bb.z, 0.f);
    float hw = fmaxf(acc.w + bb.w, 0.f);
    __half2 h0 = __floats2half2_rn(hx, hy);
    __half2 h1 = __floats2half2_rn(hz, hw);
    uint2 v = make_uint2(*(unsigned*)&h0, *(unsigned*)&h1);
    *(uint2*)&g_hh[w * 64 + lane * 2] = v;
}

// ---------------- GEMM2: g_hw4h = half(g_hh @ W4) --------------------------
__global__ void k_gemm2(const float* __restrict__ W4) {
    __shared__ float sW4[128 * 16];
    int t = threadIdx.x;
    #pragma unroll
    for (int p = 0; p < 8; p++) sW4[t + p * 256] = W4[t + p * 256];
    __syncthreads();

    int w    = (blockIdx.x * 256 + t) >> 5;
    int lane = t & 31;
    int r    = w * 2 + (lane >> 4);
    int c    = lane & 15;
    if (r >= N_NODES) return;

    const uint2* hrow = (const uint2*)&g_hh[r * 64];
    float acc = 0.f;
    #pragma unroll
    for (int kk = 0; kk < 32; kk++) {
        uint2 q = hrow[kk];
        __half2 h0 = *(__half2*)&q.x;
        __half2 h1 = *(__half2*)&q.y;
        float2 f0 = __half22float2(h0);
        float2 f1 = __half22float2(h1);
        acc = fmaf(f0.x, sW4[(kk * 4 + 0) * 16 + c], acc);
        acc = fmaf(f0.y, sW4[(kk * 4 + 1) * 16 + c], acc);
        acc = fmaf(f1.x, sW4[(kk * 4 + 2) * 16 + c], acc);
        acc = fmaf(f1.y, sW4[(kk * 4 + 3) * 16 + c], acc);
    }
    g_hw4h[r * 16 + c] = __float2half_rn(acc);
}

// ---------------- SPMM2 + b4 + log_softmax, fused --------------------------
__global__ void k_spmm2(const float* __restrict__ b4, float* __restrict__ out) {
    int t    = threadIdx.x;
    int w    = (blockIdx.x * 256 + t) >> 5;
    int lane = t & 31;
    int r    = w * 2 + (lane >> 4);
    int c    = lane & 15;
    if (r >= N_NODES) return;

    int start = g_rowstart[r];
    int deg   = g_cnt[r];
    const int2* ep = g_edge + start;
    float acc = 0.f;
    int j = 0;
    for (; j + 2 <= deg; j += 2) {
        int2 e0 = ep[j], e1 = ep[j + 1];
        float h0 = __half2float(g_hw4h[e0.x * 16 + c]);
        float h1 = __half2float(g_hw4h[e1.x * 16 + c]);
        acc = fmaf(__int_as_float(e0.y), h0, acc);
        acc = fmaf(__int_as_float(e1.y), h1, acc);
    }
    if (j < deg) {
        int2 e0 = ep[j];
        acc = fmaf(__int_as_float(e0.y), __half2float(g_hw4h[e0.x * 16 + c]), acc);
    }
    float z = acc + b4[c];

    float m = z;
    #pragma unroll
    for (int o = 1; o < 16; o <<= 1)
        m = fmaxf(m, __shfl_xor_sync(0xffffffffu, m, o, 16));
    float e = expf(z - m);
    float s = e;
    #pragma unroll
    for (int o = 1; o < 16; o <<= 1)
        s += __shfl_xor_sync(0xffffffffu, s, o, 16);
    out[r * 16 + c] = z - m - logf(s);
}

// ---------------- launch ---------------------------------------------------
extern "C" void kernel_launch(void* const* d_in, const int* in_sizes, int n_in,
                              void* d_out, int out_size) {
    const float* x    = (const float*)d_in[0];
    const float* eval = (const float*)d_in[1];
    const float* W1   = (const float*)d_in[2];
    const float* b1   = (const float*)d_in[3];
    const float* W4   = (const float*)d_in[4];
    const float* b4   = (const float*)d_in[5];
    const int*   erow = (const int*)d_in[6];
    const int*   ecol = (const int*)d_in[7];
    float*       out  = (float*)d_out;

    // One-time creation of side stream + fork/join events (host-side objects,
    // not device memory; created on the first (correctness) call, reused for
    // capture). Work DAG is identical on every call.
    static cudaStream_t s2 = nullptr;
    static cudaEvent_t evFork = nullptr, evJoin = nullptr;
    if (!s2) {
        cudaStreamCreateWithFlags(&s2, cudaStreamNonBlocking);
        cudaEventCreateWithFlags(&evFork, cudaEventDisableTiming);
        cudaEventCreateWithFlags(&evJoin, cudaEventDisableTiming);
    }

    // Fork: GEMM1 (FMA-bound) runs on s2 concurrently with the CSR build
    // (L2/atomic-bound) on the main stream.
    cudaEventRecord(evFork, 0);
    cudaStreamWaitEvent(s2, evFork, 0);
    k_gemm1<<<(N_NODES + 63) / 64, 256, 0, s2>>>(x, W1);
    cudaEventRecord(evJoin, s2);

    // CSR build on main stream
    k_zero_cnt<<<(N_NODES + 255) / 256, 256>>>();
    k_hist<<<(N_EDGES + 255) / 256, 256>>>(erow);
    k_scan1<<<SCAN_NBLK, 1024>>>();
    k_scan23<<<SCAN_NBLK, 1024>>>();
    k_scatter<<<(N_EDGES + 255) / 256, 256>>>(erow, ecol, eval);

    // Join: SPMM1 needs both GEMM1 output and the CSR.
    cudaStreamWaitEvent(0, evJoin, 0);

    k_spmm1<<<(N_NODES * 32 + 255) / 256, 256>>>(b1);
    k_gemm2<<<((N_NODES + 1) / 2 * 32 + 255) / 256, 256>>>(W4);
    k_spmm2<<<((N_NODES + 1) / 2 * 32 + 255) / 256, 256>>>(b4, out);
}

// round 5
// speedup vs baseline: 1.4433x; 1.1894x over previous
#include <cuda_runtime.h>
#include <cuda_fp16.h>
#include <cstdint>

#define N_NODES 100000
#define N_EDGES 3200000
#define N_FEAT  128
#define N_HID   128
#define N_CLASS 16
#define SCAN_NBLK 98     // ceil(100000/1024)
#define GEMM1_TILES 782  // ceil(100000/128)
#define LDM 136          // padded smem row length in halves (conflict-free)

// ---------------- scratch (device globals; no runtime allocation) ----------
__device__ unsigned int g_xw1h[N_NODES * 64];   // x@W1 as half2 pairs (128 halves/row)
__device__ __half g_w1t[128 * 128];             // W1^T in fp16: [n][k]
__device__ __half g_hw4h[N_NODES * N_CLASS];    // h@W4 as half
__device__ int2  g_edge[N_EDGES];               // CSR-sorted {col, val bits}
__device__ int   g_cnt[N_NODES];
__device__ int   g_rowstart[N_NODES];
__device__ int   g_wptr[N_NODES];
__device__ int   g_blocksums[SCAN_NBLK];

// ---------------- CSR build -------------------------------------------------
__global__ void k_zero_cnt() {
    int i = blockIdx.x * blockDim.x + threadIdx.x;
    if (i < N_NODES) g_cnt[i] = 0;
}

__global__ void k_hist(const int* __restrict__ erow) {
    int e = blockIdx.x * blockDim.x + threadIdx.x;
    if (e < N_EDGES) atomicAdd(&g_cnt[erow[e]], 1);
}

__global__ void k_scan1() {
    __shared__ int s[1024];
    int t = threadIdx.x, b = blockIdx.x;
    int i = b * 1024 + t;
    int v = (i < N_NODES) ? g_cnt[i] : 0;
    s[t] = v;
    __syncthreads();
    #pragma unroll
    for (int off = 1; off < 1024; off <<= 1) {
        int add = (t >= off) ? s[t - off] : 0;
        __syncthreads();
        s[t] += add;
        __syncthreads();
    }
    if (i < N_NODES) g_rowstart[i] = s[t] - v;
    if (t == 1023) g_blocksums[b] = s[1023];
}

__global__ void k_scan23() {
    __shared__ int s[128];
    int t = threadIdx.x, b = blockIdx.x;
    if (t < 128) s[t] = (t < SCAN_NBLK) ? g_blocksums[t] : 0;
    __syncthreads();
    #pragma unroll
    for (int off = 1; off < 128; off <<= 1) {
        int add = (t >= off && t < 128) ? s[t - off] : 0;
        __syncthreads();
        if (t < 128) s[t] += add;
        __syncthreads();
    }
    int boff = (b == 0) ? 0 : s[b - 1];
    int i = b * 1024 + t;
    if (i < N_NODES) {
        int v = g_rowstart[i] + boff;
        g_rowstart[i] = v;
        g_wptr[i] = v;
    }
}

__global__ void k_scatter(const int* __restrict__ erow,
                          const int* __restrict__ ecol,
                          const float* __restrict__ eval) {
    int e = blockIdx.x * blockDim.x + threadIdx.x;
    if (e >= N_EDGES) return;
    int r = erow[e];
    int p = atomicAdd(&g_wptr[r], 1);
    g_edge[p] = make_int2(ecol[e], __float_as_int(eval[e]));
}

// ---------------- prep: W1^T -> fp16 ----------------------------------------
__global__ void k_prep_w1(const float* __restrict__ W1) {
    int i = blockIdx.x * 256 + threadIdx.x;   // 64 x 256 = 16384
    int k = i >> 7, n = i & 127;
    g_w1t[n * 128 + k] = __float2half_rn(W1[i]);
}

// ---------------- GEMM1 (HMMA): g_xw1h = half(x @ W1) -----------------------
// Block: 256 threads (8 warps), tile 128(M) x 128(N), K=128.
// Warp grid 4(M) x 2(N): each warp 32x64. mma.sync m16n8k16 f16->f32.
__global__ void k_gemm1_mma(const float* __restrict__ x) {
    extern __shared__ __half smem[];
    __half* As = smem;                 // [128][LDM]
    __half* Bs = smem + 128 * LDM;     // [128][LDM]  (Bs[n][k] = W1[k][n])

    int t = threadIdx.x;
    int m0 = blockIdx.x * 128;

    // stage B: copy g_w1t rows (contig k) into padded smem; 128 rows x 16 uint4
    for (int i = t; i < 2048; i += 256) {
        int n = i >> 4, q = i & 15;
        *(uint4*)&Bs[n * LDM + q * 8] = ((const uint4*)g_w1t)[n * 16 + q];
    }
    // stage A: x fp32 -> fp16; 128 rows x 32 float4
    for (int i = t; i < 4096; i += 256) {
        int row = i >> 5, c4 = i & 31;
        int gm = m0 + row;
        float4 v = make_float4(0.f, 0.f, 0.f, 0.f);
        if (gm < N_NODES) v = *(const float4*)&x[gm * 128 + c4 * 4];
        __half2 h0 = __floats2half2_rn(v.x, v.y);
        __half2 h1 = __floats2half2_rn(v.z, v.w);
        *(uint2*)&As[row * LDM + c4 * 4] = make_uint2(*(unsigned*)&h0, *(unsigned*)&h1);
    }
    __syncthreads();

    int wid  = t >> 5, lane = t & 31;
    int mw   = (wid & 3) * 32;        // warp M offset
    int nw   = (wid >> 2) * 64;       // warp N offset
    int g    = lane >> 2;             // groupID 0..7
    int tid4 = lane & 3;              // 0..3

    float acc[2][8][4];
    #pragma unroll
    for (int mt = 0; mt < 2; mt++)
        #pragma unroll
        for (int nt = 0; nt < 8; nt++)
            #pragma unroll
            for (int q = 0; q < 4; q++) acc[mt][nt][q] = 0.f;

    #pragma unroll
    for (int ks = 0; ks < 8; ks++) {
        int k0 = ks * 16;
        uint32_t a[2][4];
        #pragma unroll
        for (int mt = 0; mt < 2; mt++) {
            const __half* ab = &As[(mw + mt * 16 + g) * LDM + k0 + tid4 * 2];
            a[mt][0] = *(const uint32_t*)ab;                  // (g,   k)
            a[mt][1] = *(const uint32_t*)(ab + 8 * LDM);      // (g+8, k)
            a[mt][2] = *(const uint32_t*)(ab + 8);            // (g,   k+8)
            a[mt][3] = *(const uint32_t*)(ab + 8 * LDM + 8);  // (g+8, k+8)
        }
        #pragma unroll
        for (int nt = 0; nt < 8; nt++) {
            const __half* bb = &Bs[(nw + nt * 8 + g) * LDM + k0 + tid4 * 2];
            uint32_t b0 = *(const uint32_t*)bb;          // (k..k+1,   n)
            uint32_t b1 = *(const uint32_t*)(bb + 8);    // (k+8..k+9, n)
            #pragma unroll
            for (int mt = 0; mt < 2; mt++) {
                asm volatile(
                    "mma.sync.aligned.m16n8k16.row.col.f32.f16.f16.f32 "
                    "{%0,%1,%2,%3}, {%4,%5,%6,%7}, {%8,%9}, {%0,%1,%2,%3};"
                    : "+f"(acc[mt][nt][0]), "+f"(acc[mt][nt][1]),
                      "+f"(acc[mt][nt][2]), "+f"(acc[mt][nt][3])
                    : "r"(a[mt][0]), "r"(a[mt][1]), "r"(a[mt][2]), "r"(a[mt][3]),
                      "r"(b0), "r"(b1));
            }
        }
    }

    // epilogue: D (g, tid4*2|+1) and (g+8, ...) -> half2 direct to g_xw1h
    #pragma unroll
    for (int mt = 0; mt < 2; mt++) {
        int r0 = m0 + mw + mt * 16 + g;
        #pragma unroll
        for (int nt = 0; nt < 8; nt++) {
            int cidx = (nw + nt * 8 + tid4 * 2) >> 1;   // half2 index
            if (r0 < N_NODES) {
                __half2 h = __floats2half2_rn(acc[mt][nt][0], acc[mt][nt][1]);
                g_xw1h[r0 * 64 + cidx] = *(unsigned*)&h;
            }
            if (r0 + 8 < N_NODES) {
                __half2 h = __floats2half2_rn(acc[mt][nt][2], acc[mt][nt][3]);
                g_xw1h[(r0 + 8) * 64 + cidx] = *(unsigned*)&h;
            }
        }
    }
}

// ---------------- SPMM1 + GEMM2 fused ---------------------------------------
// 512 threads, 16 rows/block. Phase 1: warp-per-row aggregate -> smem h.
// Phase 2: block GEMM h[16x128] @ W4[128x16] -> g_hw4h (fp16).
__device__ __forceinline__ void fma_row(float4& acc, float v, uint2 q) {
    float2 f0 = __half22float2(*(__half2*)&q.x);
    float2 f1 = __half22float2(*(__half2*)&q.y);
    acc.x = fmaf(v, f0.x, acc.x);
    acc.y = fmaf(v, f0.y, acc.y);
    acc.z = fmaf(v, f1.x, acc.z);
    acc.w = fmaf(v, f1.y, acc.w);
}

__global__ void k_spmm1f(const float* __restrict__ b1, const float* __restrict__ W4) {
    __shared__ float sh_h[16][128];
    __shared__ float sW4[128 * 16];
    int t = threadIdx.x;
    #pragma unroll
    for (int p = 0; p < 4; p++) sW4[t + p * 512] = W4[t + p * 512];

    int wr   = t >> 5;
    int lane = t & 31;
    int row  = blockIdx.x * 16 + wr;     // grid 6250 x 16 = 100000 exactly

    {
        int start = g_rowstart[row];
        int deg   = g_cnt[row];
        const int2* ep = g_edge + start;
        float4 acc = make_float4(0.f, 0.f, 0.f, 0.f);
        int j = 0;
        for (; j + 4 <= deg; j += 4) {
            int2 e0 = ep[j], e1 = ep[j + 1], e2 = ep[j + 2], e3 = ep[j + 3];
            uint2 q0 = *(const uint2*)&g_xw1h[e0.x * 64 + lane * 2];
            uint2 q1 = *(const uint2*)&g_xw1h[e1.x * 64 + lane * 2];
            uint2 q2 = *(const uint2*)&g_xw1h[e2.x * 64 + lane * 2];
            uint2 q3 = *(const uint2*)&g_xw1h[e3.x * 64 + lane * 2];
            fma_row(acc, __int_as_float(e0.y), q0);
            fma_row(acc, __int_as_float(e1.y), q1);
            fma_row(acc, __int_as_float(e2.y), q2);
            fma_row(acc, __int_as_float(e3.y), q3);
        }
        for (; j < deg; j++) {
            int2 e0 = ep[j];
            uint2 q0 = *(const uint2*)&g_xw1h[e0.x * 64 + lane * 2];
            fma_row(acc, __int_as_float(e0.y), q0);
        }
        float4 bb = *(const float4*)&b1[lane * 4];
        float4 h;
        h.x = fmaxf(acc.x + bb.x, 0.f);
        h.y = fmaxf(acc.y + bb.y, 0.f);
        h.z = fmaxf(acc.z + bb.z, 0.f);
        h.w = fmaxf(acc.w + bb.w, 0.f);
        *(float4*)&sh_h[wr][lane * 4] = h;
    }
    __syncthreads();

    if (t < 256) {
        int r = t >> 4, c = t & 15;
        float acc = 0.f;
        #pragma unroll
        for (int k = 0; k < 128; k += 4) {
            float4 hv = *(const float4*)&sh_h[r][k];
            acc = fmaf(hv.x, sW4[(k + 0) * 16 + c], acc);
            acc = fmaf(hv.y, sW4[(k + 1) * 16 + c], acc);
            acc = fmaf(hv.z, sW4[(k + 2) * 16 + c], acc);
            acc = fmaf(hv.w, sW4[(k + 3) * 16 + c], acc);
        }
        g_hw4h[(blockIdx.x * 16 + r) * 16 + c] = __float2half_rn(acc);
    }
}

// ---------------- SPMM2 + b4 + log_softmax, fused ---------------------------
__global__ void k_spmm2(const float* __restrict__ b4, float* __restrict__ out) {
    int t    = threadIdx.x;
    int w    = (blockIdx.x * 256 + t) >> 5;
    int lane = t & 31;
    int r    = w * 2 + (lane >> 4);
    int c    = lane & 15;
    if (r >= N_NODES) return;

    int start = g_rowstart[r];
    int deg   = g_cnt[r];
    const int2* ep = g_edge + start;
    float acc = 0.f;
    int j = 0;
    for (; j + 2 <= deg; j += 2) {
        int2 e0 = ep[j], e1 = ep[j + 1];
        float h0 = __half2float(g_hw4h[e0.x * 16 + c]);
        float h1 = __half2float(g_hw4h[e1.x * 16 + c]);
        acc = fmaf(__int_as_float(e0.y), h0, acc);
        acc = fmaf(__int_as_float(e1.y), h1, acc);
    }
    if (j < deg) {
        int2 e0 = ep[j];
        acc = fmaf(__int_as_float(e0.y), __half2float(g_hw4h[e0.x * 16 + c]), acc);
    }
    float z = acc + b4[c];

    float m = z;
    #pragma unroll
    for (int o = 1; o < 16; o <<= 1)
        m = fmaxf(m, __shfl_xor_sync(0xffffffffu, m, o, 16));
    float e = expf(z - m);
    float s = e;
    #pragma unroll
    for (int o = 1; o < 16; o <<= 1)
        s += __shfl_xor_sync(0xffffffffu, s, o, 16);
    out[r * 16 + c] = z - m - logf(s);
}

// ---------------- launch -----------------------------------------------------
extern "C" void kernel_launch(void* const* d_in, const int* in_sizes, int n_in,
                              void* d_out, int out_size) {
    const float* x    = (const float*)d_in[0];
    const float* eval = (const float*)d_in[1];
    const float* W1   = (const float*)d_in[2];
    const float* b1   = (const float*)d_in[3];
    const float* W4   = (const float*)d_in[4];
    const float* b4   = (const float*)d_in[5];
    const int*   erow = (const int*)d_in[6];
    const int*   ecol = (const int*)d_in[7];
    float*       out  = (float*)d_out;

    const int GEMM1_SMEM = 2 * 128 * LDM * 2;   // 69632 bytes

    static cudaStream_t s2 = nullptr;
    static cudaEvent_t evFork = nullptr, evJoin = nullptr;
    if (!s2) {
        cudaStreamCreateWithFlags(&s2, cudaStreamNonBlocking);
        cudaEventCreateWithFlags(&evFork, cudaEventDisableTiming);
        cudaEventCreateWithFlags(&evJoin, cudaEventDisableTiming);
        cudaFuncSetAttribute(k_gemm1_mma,
                             cudaFuncAttributeMaxDynamicSharedMemorySize, GEMM1_SMEM);
    }

    // Fork: prep + HMMA GEMM1 on s2; CSR build on main stream.
    cudaEventRecord(evFork, 0);
    cudaStreamWaitEvent(s2, evFork, 0);
    k_prep_w1<<<64, 256, 0, s2>>>(W1);
    k_gemm1_mma<<<GEMM1_TILES, 256, GEMM1_SMEM, s2>>>(x);
    cudaEventRecord(evJoin, s2);

    k_zero_cnt<<<(N_NODES + 255) / 256, 256>>>();
    k_hist<<<(N_EDGES + 255) / 256, 256>>>(erow);
    k_scan1<<<SCAN_NBLK, 1024>>>();
    k_scan23<<<SCAN_NBLK, 1024>>>();
    k_scatter<<<(N_EDGES + 255) / 256, 256>>>(erow, ecol, eval);

    cudaStreamWaitEvent(0, evJoin, 0);

    k_spmm1f<<<N_NODES / 16, 512>>>(b1, W4);
    k_spmm2<<<((N_NODES + 1) / 2 * 32 + 255) / 256, 256>>>(b4, out);
}

// round 6
// speedup vs baseline: 1.5170x; 1.0511x over previous
#include <cuda_runtime.h>
#include <cuda_fp16.h>
#include <cstdint>

#define N_NODES 100000
#define N_EDGES 3200000
#define N_FEAT  128
#define N_HID   128
#define N_CLASS 16
#define SCAN_NBLK 98     // ceil(100000/1024)
#define GEMM1_TILES 782  // ceil(100000/128)
#define LDM 136          // padded smem row length in halves (conflict-free)

// ---------------- scratch (device globals; no runtime allocation) ----------
__device__ uint32_t g_xw1q[N_NODES * 32];       // x@W1 as e4m3, 128B per row
__device__ __half g_w1t[128 * 128];             // W1^T in fp16: [n][k]
__device__ __half g_hw4h[N_NODES * N_CLASS];    // h@W4 as half
__device__ int2  g_edge[N_EDGES];               // CSR-sorted {col, val bits}
__device__ int   g_cnt[N_NODES];
__device__ int   g_rowstart[N_NODES];
__device__ int   g_wptr[N_NODES];
__device__ int   g_blocksums[SCAN_NBLK];

// ---------------- fp8 helpers -----------------------------------------------
__device__ __forceinline__ unsigned short pack_e4m3(float lo, float hi) {
    unsigned short s;
    asm("cvt.rn.satfinite.e4m3x2.f32 %0, %1, %2;" : "=h"(s) : "f"(hi), "f"(lo));
    return s;
}
__device__ __forceinline__ uint32_t e4m3x2_to_h2(unsigned short s) {
    uint32_t r;
    asm("cvt.rn.f16x2.e4m3x2 %0, %1;" : "=r"(r) : "h"(s));
    return r;
}

// ---------------- CSR build -------------------------------------------------
__global__ void k_zero_cnt() {
    int i = blockIdx.x * blockDim.x + threadIdx.x;
    if (i < N_NODES) g_cnt[i] = 0;
}

// 4 edges per thread (int4) for MLP
__global__ void k_hist(const int4* __restrict__ erow4) {
    int e = blockIdx.x * blockDim.x + threadIdx.x;
    if (e < N_EDGES / 4) {
        int4 v = erow4[e];
        atomicAdd(&g_cnt[v.x], 1);
        atomicAdd(&g_cnt[v.y], 1);
        atomicAdd(&g_cnt[v.z], 1);
        atomicAdd(&g_cnt[v.w], 1);
    }
}

__global__ void k_scan1() {
    __shared__ int s[1024];
    int t = threadIdx.x, b = blockIdx.x;
    int i = b * 1024 + t;
    int v = (i < N_NODES) ? g_cnt[i] : 0;
    s[t] = v;
    __syncthreads();
    #pragma unroll
    for (int off = 1; off < 1024; off <<= 1) {
        int add = (t >= off) ? s[t - off] : 0;
        __syncthreads();
        s[t] += add;
        __syncthreads();
    }
    if (i < N_NODES) g_rowstart[i] = s[t] - v;
    if (t == 1023) g_blocksums[b] = s[1023];
}

__global__ void k_scan23() {
    __shared__ int s[128];
    int t = threadIdx.x, b = blockIdx.x;
    if (t < 128) s[t] = (t < SCAN_NBLK) ? g_blocksums[t] : 0;
    __syncthreads();
    #pragma unroll
    for (int off = 1; off < 128; off <<= 1) {
        int add = (t >= off && t < 128) ? s[t - off] : 0;
        __syncthreads();
        if (t < 128) s[t] += add;
        __syncthreads();
    }
    int boff = (b == 0) ? 0 : s[b - 1];
    int i = b * 1024 + t;
    if (i < N_NODES) {
        int v = g_rowstart[i] + boff;
        g_rowstart[i] = v;
        g_wptr[i] = v;
    }
}

// 2 edges per thread
__global__ void k_scatter(const int2* __restrict__ erow2,
                          const int2* __restrict__ ecol2,
                          const float2* __restrict__ eval2) {
    int e = blockIdx.x * blockDim.x + threadIdx.x;
    if (e >= N_EDGES / 2) return;
    int2   r = erow2[e];
    int2   c = ecol2[e];
    float2 v = eval2[e];
    int p0 = atomicAdd(&g_wptr[r.x], 1);
    g_edge[p0] = make_int2(c.x, __float_as_int(v.x));
    int p1 = atomicAdd(&g_wptr[r.y], 1);
    g_edge[p1] = make_int2(c.y, __float_as_int(v.y));
}

// ---------------- prep: W1^T -> fp16 ----------------------------------------
__global__ void k_prep_w1(const float* __restrict__ W1) {
    int i = blockIdx.x * 256 + threadIdx.x;   // 64 x 256 = 16384
    int k = i >> 7, n = i & 127;
    g_w1t[n * 128 + k] = __float2half_rn(W1[i]);
}

// ---------------- GEMM1 (HMMA): g_xw1q = e4m3(x @ W1) -----------------------
// Block: 256 threads (8 warps), tile 128(M) x 128(N), K=128.
// Warp grid 4(M) x 2(N): each warp 32x64. mma.sync m16n8k16 f16->f32.
__global__ void k_gemm1_mma(const float* __restrict__ x) {
    extern __shared__ __half smem[];
    __half* As = smem;                 // [128][LDM]
    __half* Bs = smem + 128 * LDM;     // [128][LDM]  (Bs[n][k] = W1[k][n])

    int t = threadIdx.x;
    int m0 = blockIdx.x * 128;

    for (int i = t; i < 2048; i += 256) {
        int n = i >> 4, q = i & 15;
        *(uint4*)&Bs[n * LDM + q * 8] = ((const uint4*)g_w1t)[n * 16 + q];
    }
    for (int i = t; i < 4096; i += 256) {
        int row = i >> 5, c4 = i & 31;
        int gm = m0 + row;
        float4 v = make_float4(0.f, 0.f, 0.f, 0.f);
        if (gm < N_NODES) v = *(const float4*)&x[gm * 128 + c4 * 4];
        __half2 h0 = __floats2half2_rn(v.x, v.y);
        __half2 h1 = __floats2half2_rn(v.z, v.w);
        *(uint2*)&As[row * LDM + c4 * 4] = make_uint2(*(unsigned*)&h0, *(unsigned*)&h1);
    }
    __syncthreads();

    int wid  = t >> 5, lane = t & 31;
    int mw   = (wid & 3) * 32;
    int nw   = (wid >> 2) * 64;
    int g    = lane >> 2;
    int tid4 = lane & 3;

    float acc[2][8][4];
    #pragma unroll
    for (int mt = 0; mt < 2; mt++)
        #pragma unroll
        for (int nt = 0; nt < 8; nt++)
            #pragma unroll
            for (int q = 0; q < 4; q++) acc[mt][nt][q] = 0.f;

    #pragma unroll
    for (int ks = 0; ks < 8; ks++) {
        int k0 = ks * 16;
        uint32_t a[2][4];
        #pragma unroll
        for (int mt = 0; mt < 2; mt++) {
            const __half* ab = &As[(mw + mt * 16 + g) * LDM + k0 + tid4 * 2];
            a[mt][0] = *(const uint32_t*)ab;
            a[mt][1] = *(const uint32_t*)(ab + 8 * LDM);
            a[mt][2] = *(const uint32_t*)(ab + 8);
            a[mt][3] = *(const uint32_t*)(ab + 8 * LDM + 8);
        }
        #pragma unroll
        for (int nt = 0; nt < 8; nt++) {
            const __half* bb = &Bs[(nw + nt * 8 + g) * LDM + k0 + tid4 * 2];
            uint32_t b0 = *(const uint32_t*)bb;
            uint32_t b1 = *(const uint32_t*)(bb + 8);
            #pragma unroll
            for (int mt = 0; mt < 2; mt++) {
                asm volatile(
                    "mma.sync.aligned.m16n8k16.row.col.f32.f16.f16.f32 "
                    "{%0,%1,%2,%3}, {%4,%5,%6,%7}, {%8,%9}, {%0,%1,%2,%3};"
                    : "+f"(acc[mt][nt][0]), "+f"(acc[mt][nt][1]),
                      "+f"(acc[mt][nt][2]), "+f"(acc[mt][nt][3])
                    : "r"(a[mt][0]), "r"(a[mt][1]), "r"(a[mt][2]), "r"(a[mt][3]),
                      "r"(b0), "r"(b1));
            }
        }
    }

    // epilogue: quantize fp32 pairs -> e4m3x2, 16-bit stores
    unsigned short* xq = (unsigned short*)g_xw1q;
    #pragma unroll
    for (int mt = 0; mt < 2; mt++) {
        int r0 = m0 + mw + mt * 16 + g;
        #pragma unroll
        for (int nt = 0; nt < 8; nt++) {
            int cp = (nw + nt * 8 + tid4 * 2) >> 1;   // e4m3 pair index (0..63)
            if (r0 < N_NODES)
                xq[r0 * 64 + cp] = pack_e4m3(acc[mt][nt][0], acc[mt][nt][1]);
            if (r0 + 8 < N_NODES)
                xq[(r0 + 8) * 64 + cp] = pack_e4m3(acc[mt][nt][2], acc[mt][nt][3]);
        }
    }
}

// ---------------- SPMM1 + GEMM2 fused ---------------------------------------
// 512 threads, 16 rows/block. Phase 1: warp-per-row aggregate (fp8 gather).
// Phase 2: block GEMM h[16x128] @ W4[128x16] -> g_hw4h (fp16).
__device__ __forceinline__ void fma_row8(float4& acc, float v, uint32_t q) {
    uint32_t h01 = e4m3x2_to_h2((unsigned short)q);
    uint32_t h23 = e4m3x2_to_h2((unsigned short)(q >> 16));
    float2 f0 = __half22float2(*(__half2*)&h01);
    float2 f1 = __half22float2(*(__half2*)&h23);
    acc.x = fmaf(v, f0.x, acc.x);
    acc.y = fmaf(v, f0.y, acc.y);
    acc.z = fmaf(v, f1.x, acc.z);
    acc.w = fmaf(v, f1.y, acc.w);
}

__global__ void k_spmm1f(const float* __restrict__ b1, const float* __restrict__ W4) {
    __shared__ float sh_h[16][128];
    __shared__ float sW4[128 * 16];
    int t = threadIdx.x;
    #pragma unroll
    for (int p = 0; p < 4; p++) sW4[t + p * 512] = W4[t + p * 512];

    int wr   = t >> 5;
    int lane = t & 31;
    int row  = blockIdx.x * 16 + wr;     // grid 6250 x 16 = 100000 exactly

    {
        int start = g_rowstart[row];
        int deg   = g_cnt[row];
        const int2* ep = g_edge + start;
        float4 acc = make_float4(0.f, 0.f, 0.f, 0.f);
        int j = 0;
        for (; j + 4 <= deg; j += 4) {
            int2 e0 = ep[j], e1 = ep[j + 1], e2 = ep[j + 2], e3 = ep[j + 3];
            uint32_t q0 = g_xw1q[e0.x * 32 + lane];
            uint32_t q1 = g_xw1q[e1.x * 32 + lane];
            uint32_t q2 = g_xw1q[e2.x * 32 + lane];
            uint32_t q3 = g_xw1q[e3.x * 32 + lane];
            fma_row8(acc, __int_as_float(e0.y), q0);
            fma_row8(acc, __int_as_float(e1.y), q1);
            fma_row8(acc, __int_as_float(e2.y), q2);
            fma_row8(acc, __int_as_float(e3.y), q3);
        }
        for (; j < deg; j++) {
            int2 e0 = ep[j];
            uint32_t q0 = g_xw1q[e0.x * 32 + lane];
            fma_row8(acc, __int_as_float(e0.y), q0);
        }
        float4 bb = *(const float4*)&b1[lane * 4];
        float4 h;
        h.x = fmaxf(acc.x + bb.x, 0.f);
        h.y = fmaxf(acc.y + bb.y, 0.f);
        h.z = fmaxf(acc.z + bb.z, 0.f);
        h.w = fmaxf(acc.w + bb.w, 0.f);
        *(float4*)&sh_h[wr][lane * 4] = h;
    }
    __syncthreads();

    if (t < 256) {
        int r = t >> 4, c = t & 15;
        float acc = 0.f;
        #pragma unroll
        for (int k = 0; k < 128; k += 4) {
            float4 hv = *(const float4*)&sh_h[r][k];
            acc = fmaf(hv.x, sW4[(k + 0) * 16 + c], acc);
            acc = fmaf(hv.y, sW4[(k + 1) * 16 + c], acc);
            acc = fmaf(hv.z, sW4[(k + 2) * 16 + c], acc);
            acc = fmaf(hv.w, sW4[(k + 3) * 16 + c], acc);
        }
        g_hw4h[(blockIdx.x * 16 + r) * 16 + c] = __float2half_rn(acc);
    }
}

// ---------------- SPMM2 + b4 + log_softmax, fused ---------------------------
__global__ void k_spmm2(const float* __restrict__ b4, float* __restrict__ out) {
    int t    = threadIdx.x;
    int w    = (blockIdx.x * 256 + t) >> 5;
    int lane = t & 31;
    int r    = w * 2 + (lane >> 4);
    int c    = lane & 15;
    if (r >= N_NODES) return;

    int start = g_rowstart[r];
    int deg   = g_cnt[r];
    const int2* ep = g_edge + start;
    float acc = 0.f;
    int j = 0;
    for (; j + 2 <= deg; j += 2) {
        int2 e0 = ep[j], e1 = ep[j + 1];
        float h0 = __half2float(g_hw4h[e0.x * 16 + c]);
        float h1 = __half2float(g_hw4h[e1.x * 16 + c]);
        acc = fmaf(__int_as_float(e0.y), h0, acc);
        acc = fmaf(__int_as_float(e1.y), h1, acc);
    }
    if (j < deg) {
        int2 e0 = ep[j];
        acc = fmaf(__int_as_float(e0.y), __half2float(g_hw4h[e0.x * 16 + c]), acc);
    }
    float z = acc + b4[c];

    float m = z;
    #pragma unroll
    for (int o = 1; o < 16; o <<= 1)
        m = fmaxf(m, __shfl_xor_sync(0xffffffffu, m, o, 16));
    float e = expf(z - m);
    float s = e;
    #pragma unroll
    for (int o = 1; o < 16; o <<= 1)
        s += __shfl_xor_sync(0xffffffffu, s, o, 16);
    out[r * 16 + c] = z - m - logf(s);
}

// ---------------- launch -----------------------------------------------------
extern "C" void kernel_launch(void* const* d_in, const int* in_sizes, int n_in,
                              void* d_out, int out_size) {
    const float* x    = (const float*)d_in[0];
    const float* eval = (const float*)d_in[1];
    const float* W1   = (const float*)d_in[2];
    const float* b1   = (const float*)d_in[3];
    const float* W4   = (const float*)d_in[4];
    const float* b4   = (const float*)d_in[5];
    const int*   erow = (const int*)d_in[6];
    const int*   ecol = (const int*)d_in[7];
    float*       out  = (float*)d_out;

    const int GEMM1_SMEM = 2 * 128 * LDM * 2;   // 69632 bytes

    static cudaStream_t s2 = nullptr;
    static cudaEvent_t evFork = nullptr, evJoin = nullptr;
    if (!s2) {
        cudaStreamCreateWithFlags(&s2, cudaStreamNonBlocking);
        cudaEventCreateWithFlags(&evFork, cudaEventDisableTiming);
        cudaEventCreateWithFlags(&evJoin, cudaEventDisableTiming);
        cudaFuncSetAttribute(k_gemm1_mma,
                             cudaFuncAttributeMaxDynamicSharedMemorySize, GEMM1_SMEM);
    }

    // Fork: prep + HMMA GEMM1 on s2; CSR build on main stream.
    cudaEventRecord(evFork, 0);
    cudaStreamWaitEvent(s2, evFork, 0);
    k_prep_w1<<<64, 256, 0, s2>>>(W1);
    k_gemm1_mma<<<GEMM1_TILES, 256, GEMM1_SMEM, s2>>>(x);
    cudaEventRecord(evJoin, s2);

    k_zero_cnt<<<(N_NODES + 255) / 256, 256>>>();
    k_hist<<<(N_EDGES / 4 + 255) / 256, 256>>>((const int4*)erow);
    k_scan1<<<SCAN_NBLK, 1024>>>();
    k_scan23<<<SCAN_NBLK, 1024>>>();
    k_scatter<<<(N_EDGES / 2 + 255) / 256, 256>>>((const int2*)erow,
                                                  (const int2*)ecol,
                                                  (const float2*)eval);

    cudaStreamWaitEvent(0, evJoin, 0);

    k_spmm1f<<<N_NODES / 16, 512>>>(b1, W4);
    k_spmm2<<<((N_NODES + 1) / 2 * 32 + 255) / 256, 256>>>(b4, out);
}